// round 1
// baseline (speedup 1.0000x reference)
#include <cuda_runtime.h>
#include <cuda_bf16.h>
#include <cstdint>

#define DINLINE __device__ __forceinline__

// ---------------- problem constants ----------------
#define ROWS_TOTAL 32768      // B*N = 8*4096
#define CDIM 768
#define NB 8
#define BS 96
#define INV_NTOT (1.0f/25165824.0f)   // 1 / (B*H*W*C)
#define LAMBDA 0.01f

// ---------------- device scratch (no cudaMalloc allowed) ----------------
__device__ __nv_bfloat16 g_cas[CDIM * CDIM];                  // 1.2 MB, symmetric
__device__ __nv_bfloat16 g_Y[(size_t)ROWS_TOTAL * CDIM];      // 50.3 MB
__device__ __nv_bfloat16 g_D[(size_t)ROWS_TOTAL * CDIM];      // 50.3 MB
__device__ __nv_bfloat16 g_W1T[NB * 192 * 96];                // [blk][n(192)][k(96)]
__device__ __nv_bfloat16 g_W2T[NB * 192 * 192];               // [blk][n(192)][k(192)]

// ---------------- mma / ldmatrix helpers ----------------
DINLINE void ldsm4(uint32_t& r0, uint32_t& r1, uint32_t& r2, uint32_t& r3, const void* p) {
    uint32_t a = (uint32_t)__cvta_generic_to_shared(p);
    asm volatile("ldmatrix.sync.aligned.m8n8.x4.shared.b16 {%0,%1,%2,%3}, [%4];"
                 : "=r"(r0), "=r"(r1), "=r"(r2), "=r"(r3) : "r"(a));
}

DINLINE void mma16816(float* c, const uint32_t* a, const uint32_t* b) {
    asm volatile("mma.sync.aligned.m16n8k16.row.col.f32.bf16.bf16.f32 "
                 "{%0,%1,%2,%3}, {%4,%5,%6,%7}, {%8,%9}, {%0,%1,%2,%3};"
                 : "+f"(c[0]), "+f"(c[1]), "+f"(c[2]), "+f"(c[3])
                 : "r"(a[0]), "r"(a[1]), "r"(a[2]), "r"(a[3]),
                   "r"(b[0]), "r"(b[1]));
}

// ---------------- prep kernels ----------------
__global__ void prep_cas() {
    int idx = blockIdx.x * blockDim.x + threadIdx.x;
    if (idx >= CDIM * CDIM) return;
    int i = idx / CDIM, j = idx % CDIM;
    int p = (int)(((long long)i * (long long)j) % CDIM);     // exact angle reduction
    float ang = (float)p * (6.28318530717958647692f / (float)CDIM);
    g_cas[idx] = __float2bfloat16(cosf(ang) + sinf(ang));
}

// W1T[blk][n][i] : B operand (N-major) for o1 = Y_blk @ [w1r | w1i]
__global__ void prep_w1(const float* __restrict__ w1) {
    int idx = blockIdx.x * blockDim.x + threadIdx.x;
    if (idx >= NB * 192 * 96) return;
    int i = idx % 96;
    int n = (idx / 96) % 192;
    int k = idx / (96 * 192);
    float v = (n < 96) ? w1[((0 * NB + k) * 96 + i) * 96 + n]
                       : w1[((1 * NB + k) * 96 + i) * 96 + (n - 96)];
    g_W1T[idx] = __float2bfloat16(v);
}

// W2T[blk][c][j] : complex 2nd layer folded into one [192,192] matrix (N-major)
//   c<96  (o2r): j<96 -> +w2r[j][c],  j>=96 -> -w2i[j-96][c]
//   c>=96 (o2i): j<96 -> +w2i[j][c'], j>=96 -> +w2r[j-96][c']
__global__ void prep_w2(const float* __restrict__ w2) {
    int idx = blockIdx.x * blockDim.x + threadIdx.x;
    if (idx >= NB * 192 * 192) return;
    int j = idx % 192;
    int c = (idx / 192) % 192;
    int k = idx / (192 * 192);
    float v;
    if (c < 96) {
        v = (j < 96) ?  w2[((0 * NB + k) * 96 + j) * 96 + c]
                     : -w2[((1 * NB + k) * 96 + (j - 96)) * 96 + c];
    } else {
        int cc = c - 96;
        v = (j < 96) ?  w2[((1 * NB + k) * 96 + j) * 96 + cc]
                     :  w2[((0 * NB + k) * 96 + (j - 96)) * 96 + cc];
    }
    g_W2T[idx] = __float2bfloat16(v);
}

// ---------------- big GEMM: [32768,768] @ cas[768,768] ----------------
// MODE 0: A = x (f32 -> bf16), writes g_Y (bf16)
// MODE 1: A = g_D (bf16), writes out = acc*INV_NTOT + x (f32)
template<int MODE>
__global__ void __launch_bounds__(256) gemm768(const float* __restrict__ Ax,
                                               const float* __restrict__ xbias,
                                               float* __restrict__ outp) {
    constexpr int BM = 128, BN = 128, BK = 32, AST = BK + 8, BST = BK + 8;
    __shared__ __nv_bfloat16 As[BM * AST];
    __shared__ __nv_bfloat16 Bs[BN * BST];
    const int m0 = blockIdx.x * BM, n0 = blockIdx.y * BN;
    const int tid = threadIdx.x, lane = tid & 31, w = tid >> 5;
    const int wm = (w & 3) * 32, wn = (w >> 2) * 64;

    float acc[2][8][4];
#pragma unroll
    for (int a = 0; a < 2; a++)
#pragma unroll
        for (int b = 0; b < 8; b++)
#pragma unroll
            for (int c = 0; c < 4; c++) acc[a][b][c] = 0.f;

#pragma unroll 1
    for (int k0 = 0; k0 < CDIM; k0 += BK) {
        __syncthreads();
        // load A tile (128x32)
#pragma unroll
        for (int e = tid; e < BM * BK / 2; e += 256) {
            int r = e >> 4, c = (e & 15) << 1;
            if (MODE == 0) {
                float2 v = *(const float2*)&Ax[(size_t)(m0 + r) * CDIM + k0 + c];
                __nv_bfloat162 h;
                h.x = __float2bfloat16(v.x);
                h.y = __float2bfloat16(v.y);
                *(__nv_bfloat162*)&As[r * AST + c] = h;
            } else {
                *(uint32_t*)&As[r * AST + c] =
                    *(const uint32_t*)&g_D[(size_t)(m0 + r) * CDIM + k0 + c];
            }
        }
        // load B tile from cas (symmetric: row n of cas == column n)
#pragma unroll
        for (int e = tid; e < BN * BK / 2; e += 256) {
            int r = e >> 4, c = (e & 15) << 1;
            *(uint32_t*)&Bs[r * BST + c] =
                *(const uint32_t*)&g_cas[(size_t)(n0 + r) * CDIM + k0 + c];
        }
        __syncthreads();
#pragma unroll
        for (int kk = 0; kk < BK; kk += 16) {
            uint32_t af[2][4];
#pragma unroll
            for (int mt = 0; mt < 2; mt++)
                ldsm4(af[mt][0], af[mt][1], af[mt][2], af[mt][3],
                      &As[(wm + mt * 16 + (lane & 15)) * AST + kk + ((lane >> 4) << 3)]);
#pragma unroll
            for (int q = 0; q < 4; q++) {
                uint32_t bfr[2][2];
                int nrow = wn + q * 16 + (lane & 7) + ((lane >> 4) & 1) * 8;
                int koff = kk + (lane & 8);
                ldsm4(bfr[0][0], bfr[0][1], bfr[1][0], bfr[1][1], &Bs[nrow * BST + koff]);
#pragma unroll
                for (int mt = 0; mt < 2; mt++) {
                    mma16816(acc[mt][2 * q + 0], af[mt], bfr[0]);
                    mma16816(acc[mt][2 * q + 1], af[mt], bfr[1]);
                }
            }
        }
    }

    const int g = lane >> 2, c2 = (lane & 3) << 1;
#pragma unroll
    for (int mt = 0; mt < 2; mt++) {
#pragma unroll
        for (int nt = 0; nt < 8; nt++) {
            int col = n0 + wn + nt * 8 + c2;
            int row = m0 + wm + mt * 16 + g;
            if (MODE == 0) {
                __nv_bfloat162 h0, h1;
                h0.x = __float2bfloat16(acc[mt][nt][0]);
                h0.y = __float2bfloat16(acc[mt][nt][1]);
                h1.x = __float2bfloat16(acc[mt][nt][2]);
                h1.y = __float2bfloat16(acc[mt][nt][3]);
                *(__nv_bfloat162*)&g_Y[(size_t)row * CDIM + col] = h0;
                *(__nv_bfloat162*)&g_Y[(size_t)(row + 8) * CDIM + col] = h1;
            } else {
                float2 xv0 = *(const float2*)&xbias[(size_t)row * CDIM + col];
                float2 xv1 = *(const float2*)&xbias[(size_t)(row + 8) * CDIM + col];
                float2 o0, o1;
                o0.x = acc[mt][nt][0] * INV_NTOT + xv0.x;
                o0.y = acc[mt][nt][1] * INV_NTOT + xv0.y;
                o1.x = acc[mt][nt][2] * INV_NTOT + xv1.x;
                o1.y = acc[mt][nt][3] * INV_NTOT + xv1.y;
                *(float2*)&outp[(size_t)row * CDIM + col] = o0;
                *(float2*)&outp[(size_t)(row + 8) * CDIM + col] = o1;
            }
        }
    }
}

// ---------------- fused block-diagonal MLP ----------------
// per CTA: 128 rows x one block (96 channels)
//   O1 = relu(Y_blk @ W1T^T + b1c)        [128,192]
//   O2 = O1 @ W2T^T + b2c                 [128,192]
//   D_blk = ss(O2[:, :96]) - ss(O2[:, 96:])
constexpr int MLP_SMEM = 196096;

__global__ void __launch_bounds__(256) mlp_kernel(const float* __restrict__ b1,
                                                  const float* __restrict__ b2) {
    extern __shared__ char smem[];
    __nv_bfloat16* Ys  = (__nv_bfloat16*)(smem);             // 128 x 104
    __nv_bfloat16* W1s = (__nv_bfloat16*)(smem + 26624);     // 192 x 104
    __nv_bfloat16* O1s = (__nv_bfloat16*)(smem + 66560);     // 128 x 200
    __nv_bfloat16* W2s = (__nv_bfloat16*)(smem + 117760);    // 192 x 200
    float* bias1 = (float*)(smem + 194560);                  // 192
    float* bias2 = bias1 + 192;                              // 192

    const int m0 = blockIdx.x * 128;
    const int blk = blockIdx.y;
    const int tid = threadIdx.x, lane = tid & 31, w = tid >> 5;
    const int wm = (w & 3) * 32, wn = (w >> 2) * 96;

    // ---- stage everything into SMEM (uint4 vectorized) ----
#pragma unroll
    for (int e = tid; e < 1536; e += 256) {           // Y tile: 128 x 12 uint4
        int r = e / 12, q = e % 12;
        *(uint4*)&Ys[r * 104 + q * 8] =
            *(const uint4*)&g_Y[(size_t)(m0 + r) * CDIM + blk * 96 + q * 8];
    }
#pragma unroll
    for (int e = tid; e < 2304; e += 256) {           // W1T: 192 x 12 uint4
        int r = e / 12, q = e % 12;
        *(uint4*)&W1s[r * 104 + q * 8] = *(const uint4*)&g_W1T[(blk * 192 + r) * 96 + q * 8];
    }
#pragma unroll
    for (int e = tid; e < 4608; e += 256) {           // W2T: 192 x 24 uint4
        int r = e / 24, q = e % 24;
        *(uint4*)&W2s[r * 200 + q * 8] = *(const uint4*)&g_W2T[(blk * 192 + r) * 192 + q * 8];
    }
    if (tid < 192) {
        bias1[tid] = (tid < 96) ? b1[blk * 96 + tid] : b1[(NB + blk) * 96 + (tid - 96)];
        bias2[tid] = (tid < 96) ? b2[blk * 96 + tid] : b2[(NB + blk) * 96 + (tid - 96)];
    }
    __syncthreads();

    const int g = lane >> 2, c2 = (lane & 3) << 1;
    float acc[2][12][4];
#pragma unroll
    for (int a = 0; a < 2; a++)
#pragma unroll
        for (int b = 0; b < 12; b++)
#pragma unroll
            for (int c = 0; c < 4; c++) acc[a][b][c] = 0.f;

    // ---- GEMM-A: [128,96] @ [96,192] ----
#pragma unroll
    for (int k0 = 0; k0 < 96; k0 += 16) {
        uint32_t af[2][4];
#pragma unroll
        for (int mt = 0; mt < 2; mt++)
            ldsm4(af[mt][0], af[mt][1], af[mt][2], af[mt][3],
                  &Ys[(wm + mt * 16 + (lane & 15)) * 104 + k0 + ((lane >> 4) << 3)]);
#pragma unroll
        for (int q = 0; q < 6; q++) {
            uint32_t bfr[2][2];
            int nrow = wn + q * 16 + (lane & 7) + ((lane >> 4) & 1) * 8;
            int koff = k0 + (lane & 8);
            ldsm4(bfr[0][0], bfr[0][1], bfr[1][0], bfr[1][1], &W1s[nrow * 104 + koff]);
#pragma unroll
            for (int mt = 0; mt < 2; mt++) {
                mma16816(acc[mt][2 * q + 0], af[mt], bfr[0]);
                mma16816(acc[mt][2 * q + 1], af[mt], bfr[1]);
            }
        }
    }
    // epilogue A: relu + bias -> O1s
#pragma unroll
    for (int mt = 0; mt < 2; mt++) {
#pragma unroll
        for (int nt = 0; nt < 12; nt++) {
            int col = wn + nt * 8 + c2;
            int r0 = wm + mt * 16 + g;
            float v0 = fmaxf(acc[mt][nt][0] + bias1[col], 0.f);
            float v1 = fmaxf(acc[mt][nt][1] + bias1[col + 1], 0.f);
            float v2 = fmaxf(acc[mt][nt][2] + bias1[col], 0.f);
            float v3 = fmaxf(acc[mt][nt][3] + bias1[col + 1], 0.f);
            __nv_bfloat162 h0, h1;
            h0.x = __float2bfloat16(v0); h0.y = __float2bfloat16(v1);
            h1.x = __float2bfloat16(v2); h1.y = __float2bfloat16(v3);
            *(__nv_bfloat162*)&O1s[r0 * 200 + col] = h0;
            *(__nv_bfloat162*)&O1s[(r0 + 8) * 200 + col] = h1;
        }
    }
    __syncthreads();

    // ---- GEMM-B: [128,192] @ [192,192] ----
#pragma unroll
    for (int a = 0; a < 2; a++)
#pragma unroll
        for (int b = 0; b < 12; b++)
#pragma unroll
            for (int c = 0; c < 4; c++) acc[a][b][c] = 0.f;

#pragma unroll
    for (int k0 = 0; k0 < 192; k0 += 16) {
        uint32_t af[2][4];
#pragma unroll
        for (int mt = 0; mt < 2; mt++)
            ldsm4(af[mt][0], af[mt][1], af[mt][2], af[mt][3],
                  &O1s[(wm + mt * 16 + (lane & 15)) * 200 + k0 + ((lane >> 4) << 3)]);
#pragma unroll
        for (int q = 0; q < 6; q++) {
            uint32_t bfr[2][2];
            int nrow = wn + q * 16 + (lane & 7) + ((lane >> 4) & 1) * 8;
            int koff = k0 + (lane & 8);
            ldsm4(bfr[0][0], bfr[0][1], bfr[1][0], bfr[1][1], &W2s[nrow * 200 + koff]);
#pragma unroll
            for (int mt = 0; mt < 2; mt++) {
                mma16816(acc[mt][2 * q + 0], af[mt], bfr[0]);
                mma16816(acc[mt][2 * q + 1], af[mt], bfr[1]);
            }
        }
    }
    __syncthreads();   // everyone done reading O1s

    // epilogue B: bias + softshrink -> O1s (reuse)
#pragma unroll
    for (int mt = 0; mt < 2; mt++) {
#pragma unroll
        for (int nt = 0; nt < 12; nt++) {
            int col = wn + nt * 8 + c2;
            int r0 = wm + mt * 16 + g;
            float v0 = acc[mt][nt][0] + bias2[col];
            float v1 = acc[mt][nt][1] + bias2[col + 1];
            float v2 = acc[mt][nt][2] + bias2[col];
            float v3 = acc[mt][nt][3] + bias2[col + 1];
            v0 = copysignf(fmaxf(fabsf(v0) - LAMBDA, 0.f), v0);
            v1 = copysignf(fmaxf(fabsf(v1) - LAMBDA, 0.f), v1);
            v2 = copysignf(fmaxf(fabsf(v2) - LAMBDA, 0.f), v2);
            v3 = copysignf(fmaxf(fabsf(v3) - LAMBDA, 0.f), v3);
            __nv_bfloat162 h0, h1;
            h0.x = __float2bfloat16(v0); h0.y = __float2bfloat16(v1);
            h1.x = __float2bfloat16(v2); h1.y = __float2bfloat16(v3);
            *(__nv_bfloat162*)&O1s[r0 * 200 + col] = h0;
            *(__nv_bfloat162*)&O1s[(r0 + 8) * 200 + col] = h1;
        }
    }
    __syncthreads();

    // combine real - imag, store D tile
#pragma unroll
    for (int e = tid; e < 128 * 48; e += 256) {
        int r = e / 48, c = (e % 48) * 2;
        float d0 = __bfloat162float(O1s[r * 200 + c]) -
                   __bfloat162float(O1s[r * 200 + 96 + c]);
        float d1 = __bfloat162float(O1s[r * 200 + c + 1]) -
                   __bfloat162float(O1s[r * 200 + 97 + c]);
        __nv_bfloat162 h;
        h.x = __float2bfloat16(d0);
        h.y = __float2bfloat16(d1);
        *(__nv_bfloat162*)&g_D[(size_t)(m0 + r) * CDIM + blk * 96 + c] = h;
    }
}

// ---------------- launch ----------------
extern "C" void kernel_launch(void* const* d_in, const int* in_sizes, int n_in,
                              void* d_out, int out_size) {
    const float* x  = (const float*)d_in[0];
    const float* w1 = (const float*)d_in[1];
    const float* b1 = (const float*)d_in[2];
    const float* w2 = (const float*)d_in[3];
    const float* b2 = (const float*)d_in[4];
    float* out = (float*)d_out;

    prep_cas<<<(CDIM * CDIM + 1023) / 1024, 1024>>>();
    prep_w1<<<(NB * 192 * 96 + 255) / 256, 256>>>(w1);
    prep_w2<<<(NB * 192 * 192 + 255) / 256, 256>>>(w2);

    gemm768<0><<<dim3(ROWS_TOTAL / 128, CDIM / 128), 256>>>(x, nullptr, nullptr);

    cudaFuncSetAttribute(mlp_kernel, cudaFuncAttributeMaxDynamicSharedMemorySize, MLP_SMEM);
    mlp_kernel<<<dim3(ROWS_TOTAL / 128, NB), 256, MLP_SMEM>>>(b1, b2);

    gemm768<1><<<dim3(ROWS_TOTAL / 128, CDIM / 128), 256>>>(nullptr, x, out);
}